// round 3
// baseline (speedup 1.0000x reference)
#include <cuda_runtime.h>

// RALoss: loss = sum_i mean_j 10*exp(-sum_{hw}(amax[i,j,hw] - aorg[i,j,hw]))
// Shapes: (4, 64, 512, 512) fp32 x2 inputs, scalar fp32 output.

#define L_DIM 4
#define B_DIM 64
#define PAIRS (L_DIM * B_DIM)        // 256
#define HW (512 * 512)               // 262144 elems per (i,j) map
#define BLKS_PER_PAIR 64
#define THREADS 256
#define F4_PER_THREAD 4              // 16 floats/thread
// per block: 256 threads * 16 = 4096 elems; * 64 blocks = 262144 = HW  (exact tiling)

__device__ float g_partials[PAIRS * BLKS_PER_PAIR];

__global__ __launch_bounds__(THREADS, 8)
void raloss_reduce_kernel(const float4* __restrict__ amax,
                          const float4* __restrict__ aorg) {
    const int blk  = blockIdx.x;           // 0..63   (chunk within pair)
    const int pair = blockIdx.y;           // 0..255
    const int tid  = threadIdx.x;

    // base offset in float4 units: pair * (HW/4) + blk * (4096/4)
    const long long base = (long long)pair * (HW / 4) + (long long)blk * (THREADS * F4_PER_THREAD);

    // Front-batched loads for MLP: 8 independent 128-bit LDGs in flight.
    float4 ma[F4_PER_THREAD];
    float4 mo[F4_PER_THREAD];
#pragma unroll
    for (int k = 0; k < F4_PER_THREAD; k++) {
        long long idx = base + tid + k * THREADS;
        ma[k] = amax[idx];
        mo[k] = aorg[idx];
    }

    float s = 0.0f;
#pragma unroll
    for (int k = 0; k < F4_PER_THREAD; k++) {
        s += (ma[k].x - mo[k].x) + (ma[k].y - mo[k].y)
           + (ma[k].z - mo[k].z) + (ma[k].w - mo[k].w);
    }

    // Warp reduce
#pragma unroll
    for (int off = 16; off > 0; off >>= 1)
        s += __shfl_xor_sync(0xFFFFFFFFu, s, off);

    // Block reduce across 8 warps
    __shared__ float warp_sums[THREADS / 32];
    const int warp = tid >> 5;
    const int lane = tid & 31;
    if (lane == 0) warp_sums[warp] = s;
    __syncthreads();

    if (warp == 0) {
        float v = (lane < (THREADS / 32)) ? warp_sums[lane] : 0.0f;
#pragma unroll
        for (int off = 4; off > 0; off >>= 1)
            v += __shfl_xor_sync(0xFFFFFFFFu, v, off);
        if (lane == 0)
            g_partials[pair * BLKS_PER_PAIR + blk] = v;
    }
}

__global__ __launch_bounds__(PAIRS)
void raloss_finalize_kernel(float* __restrict__ out) {
    const int t = threadIdx.x;  // one thread per (i,j) pair, 256 threads

    // Deterministic fixed-order sum of this pair's 64 block partials.
    float d = 0.0f;
#pragma unroll
    for (int k = 0; k < BLKS_PER_PAIR; k++)
        d += g_partials[t * BLKS_PER_PAIR + k];

    // contribution: 10 * exp(-d) / B  (mean over j, then sum over i == sum all / 64)
    float v = 10.0f * expf(-d) * (1.0f / (float)B_DIM);

    // Block reduce 256 -> 1
#pragma unroll
    for (int off = 16; off > 0; off >>= 1)
        v += __shfl_xor_sync(0xFFFFFFFFu, v, off);

    __shared__ float warp_sums[PAIRS / 32];
    const int warp = t >> 5;
    const int lane = t & 31;
    if (lane == 0) warp_sums[warp] = v;
    __syncthreads();

    if (warp == 0) {
        float w = (lane < (PAIRS / 32)) ? warp_sums[lane] : 0.0f;
#pragma unroll
        for (int off = 4; off > 0; off >>= 1)
            w += __shfl_xor_sync(0xFFFFFFFFu, w, off);
        if (lane == 0)
            out[0] = w;
    }
}

extern "C" void kernel_launch(void* const* d_in, const int* in_sizes, int n_in,
                              void* d_out, int out_size) {
    const float4* amax = (const float4*)d_in[0];
    const float4* aorg = (const float4*)d_in[1];
    float* out = (float*)d_out;

    dim3 grid(BLKS_PER_PAIR, PAIRS, 1);
    raloss_reduce_kernel<<<grid, THREADS>>>(amax, aorg);
    raloss_finalize_kernel<<<1, PAIRS>>>(out);
}